// round 8
// baseline (speedup 1.0000x reference)
#include <cuda_runtime.h>
#include <math.h>

// MHGAttend: masked multi-head "attention" (reference bug: scores use V, not K).
// N=4096, HIDDEN=256, HEADS=8, Dh=32.
// 3-launch pipeline:
//   K1 qv_pack : q = x@Wq^T+bq, v = x@Wv^T+bv (head-major [H,N,Dh]) in parallel
//                with Adj (64MB int32) -> 2MB bitmask.  Wk skipped (dead code).
//   K2 attn    : per (head, 64-row block): single-pass exp (no max subtraction,
//                scores O(10), fp32-safe; MUFU ex2.approx), packed fma.rn.f32x2
//                inner loops. Writes unnormalized p to attn, accumulates l and
//                o = p@v; then normalizes its own 1MB attn stripe IN-KERNEL
//                (stripe is block-local and L2-warm -> traffic overlaps other
//                blocks' compute instead of a separate exposed pass).
//   K3 wo      : final linear out_tmp@Wo^T+bo (256 blocks, ~30us).

#define N_TOK  4096
#define HID    256
#define HEADS  8
#define DH     32
#define BM     64
#define BN     64
#define SP     (BM + 4)              // transposed-tile row stride (68 floats)
#define VP     (DH + 4)              // row-major v tile stride (36 floats)
#define MWORDS (N_TOK / 32)
// exp2 scale: log2(e)/sqrt(32)
#define SCALE_E ((float)(1.4426950408889634 / 5.656854249492381))

typedef unsigned long long u64;

// scratch (allocation-free rule: __device__ globals)
__device__ float    g_q[HEADS * N_TOK * DH];      // 4 MB
__device__ float    g_v[HEADS * N_TOK * DH];      // 4 MB
__device__ float    g_otmp[N_TOK * HID];          // 4 MB
__device__ unsigned g_mask[N_TOK * MWORDS];       // 2 MB

// guaranteed single-MUFU exp2
__device__ __forceinline__ float ex2f(float x) {
    float y;
    asm("ex2.approx.ftz.f32 %0, %1;" : "=f"(y) : "f"(x));
    return y;
}
// packed fp32x2 FMA: d = a*b + d  (two IEEE fp32 FMAs, one instruction)
__device__ __forceinline__ void fma2(u64& d, u64 a, u64 b) {
    asm("fma.rn.f32x2 %0, %1, %2, %0;" : "+l"(d) : "l"(a), "l"(b));
}
__device__ __forceinline__ u64 pack2(float x) {
    u64 r;
    asm("mov.b64 %0, {%1, %1};" : "=l"(r) : "f"(x));
    return r;
}
__device__ __forceinline__ void unpack2(u64 v, float& lo, float& hi) {
    asm("mov.b64 {%0, %1}, %2;" : "=f"(lo), "=f"(hi) : "l"(v));
}

// ---------------------------------------------------------------- linear tile
// y = X @ W^T + b for one 64x64 output tile. Transposed smem tiles -> LDS.128.
// mode 0: dst = g_q (head layout), 1: dst = g_v (head layout),
// mode 2: X = g_otmp, dst = ext (row-major [N,HID])
__device__ __forceinline__ void linear_tile(
    const float* __restrict__ X, const float* __restrict__ W,
    const float* __restrict__ b, float* __restrict__ ext,
    int mode, int r0, int f0, int tid)
{
    __shared__ float xsT[32][SP];     // [k][row]
    __shared__ float wsT[32][SP];     // [k][feat]
    int tx = tid & 15, ty = tid >> 4;
    float acc[4][4] = {};
    for (int kc = 0; kc < HID; kc += 32) {
        for (int i = tid; i < 64 * 8; i += 256) {       // 512 float4 each tile
            int row = i >> 3, k4 = (i & 7) * 4;
            float4 tx4 = *reinterpret_cast<const float4*>(
                &X[(size_t)(r0 + row) * HID + kc + k4]);
            xsT[k4 + 0][row] = tx4.x; xsT[k4 + 1][row] = tx4.y;
            xsT[k4 + 2][row] = tx4.z; xsT[k4 + 3][row] = tx4.w;
            float4 tw4 = *reinterpret_cast<const float4*>(
                &W[(size_t)(f0 + row) * HID + kc + k4]);
            wsT[k4 + 0][row] = tw4.x; wsT[k4 + 1][row] = tw4.y;
            wsT[k4 + 2][row] = tw4.z; wsT[k4 + 3][row] = tw4.w;
        }
        __syncthreads();
#pragma unroll
        for (int k = 0; k < 32; k++) {
            float xv[4], wv[4];
            *reinterpret_cast<float4*>(xv) =
                *reinterpret_cast<const float4*>(&xsT[k][ty * 4]);
            *reinterpret_cast<float4*>(wv) =
                *reinterpret_cast<const float4*>(&wsT[k][tx * 4]);
#pragma unroll
            for (int i = 0; i < 4; i++)
#pragma unroll
                for (int j = 0; j < 4; j++) acc[i][j] += xv[i] * wv[j];
        }
        __syncthreads();
    }
    float* dstq = (mode == 0) ? g_q : g_v;
#pragma unroll
    for (int i = 0; i < 4; i++) {
        int n = r0 + ty * 4 + i;
#pragma unroll
        for (int j = 0; j < 4; j++) {
            int f = f0 + tx * 4 + j;
            float val = acc[i][j] + b[f];
            if (mode == 2)
                ext[(size_t)n * HID + f] = val;
            else
                dstq[(size_t)(f >> 5) * (N_TOK * DH) + (size_t)n * DH + (f & 31)] = val;
        }
    }
}

// ---------------------------------------------------------------- K1: qv + pack
// grid (96, 4, 2): x<64 -> linear tile (z=0: Wq->g_q, z=1: Wv->g_v);
// x>=64 -> mask pack (32 x-blocks * 4 y * 2 z * 256 thr = 65536 threads, 8 words each)
__global__ __launch_bounds__(256) void qv_pack_kernel(
    const float* __restrict__ x,
    const float* __restrict__ wq_w, const float* __restrict__ wq_b,
    const float* __restrict__ wv_w, const float* __restrict__ wv_b,
    const int* __restrict__ Adj)
{
    const int tid = threadIdx.x;
    if (blockIdx.x < 64) {
        const int mode = blockIdx.z;
        linear_tile(x, mode == 0 ? wq_w : wv_w, mode == 0 ? wq_b : wv_b,
                    nullptr, mode, blockIdx.x * 64, blockIdx.y * 64, tid);
    } else {
        int t8 = (((int)blockIdx.z * 4 + blockIdx.y) * 32 + (blockIdx.x - 64)) * 256 + tid;
        const int4* a = reinterpret_cast<const int4*>(Adj) + (size_t)t8 * 64;
#pragma unroll
        for (int wi = 0; wi < 8; wi++) {
            unsigned w = 0;
#pragma unroll
            for (int i = 0; i < 8; i++) {
                int4 q = a[wi * 8 + i];
                w |= (unsigned)(q.x != 0) << (i * 4 + 0);
                w |= (unsigned)(q.y != 0) << (i * 4 + 1);
                w |= (unsigned)(q.z != 0) << (i * 4 + 2);
                w |= (unsigned)(q.w != 0) << (i * 4 + 3);
            }
            g_mask[t8 * 8 + wi] = w;
        }
    }
}

// ---------------------------------------------------------------- K2: attention
// Single pass per (head, 64-row block): p = exp(masked scaled score)
// (unnormalized), write p to attn, l += row sums, o += p @ v.  FFMA2 inner
// loops. Tail: normalize this block's own attn stripe in place.
__global__ __launch_bounds__(256) void attn_kernel(float* __restrict__ attn_out,
                                                   int write_attn)
{
    const int h = blockIdx.y;
    const int r0 = blockIdx.x * BM;
    const float* qh = g_q + (size_t)h * N_TOK * DH;
    const float* vh = g_v + (size_t)h * N_TOK * DH;

    __shared__ float qsT[DH][SP];        // [k][row]   (score GEMM, LDS.128)
    __shared__ float vsT[DH][SP];        // [k][col]   (score GEMM, LDS.128)
    __shared__ float vs[BN][VP];         // [col][k]   (o GEMM, LDS.128)
    __shared__ float ps[BM][SP];         // p tile for the o-GEMM
    __shared__ float red[BM][17];
    __shared__ float l_s[BM];

    const int tid = threadIdx.x, tx = tid & 15, ty = tid >> 4;

    // load q tile transposed, pre-scaled by log2e/sqrt(Dh)
    for (int i = tid; i < BM * DH / 4; i += 256) {
        int row = i >> 3;                // 8 float4 per row
        int k4  = (i & 7) * 4;
        float4 t4 = *reinterpret_cast<const float4*>(&qh[(size_t)(r0 + row) * DH + k4]);
        qsT[k4 + 0][row] = t4.x * SCALE_E; qsT[k4 + 1][row] = t4.y * SCALE_E;
        qsT[k4 + 2][row] = t4.z * SCALE_E; qsT[k4 + 3][row] = t4.w * SCALE_E;
    }
    if (tid < BM) l_s[tid] = 0.f;
    __syncthreads();

    u64 o2[4] = {0ull, 0ull, 0ull, 0ull};      // 8 packed fp32 accumulators
    const int orow = tid >> 2;           // 0..63
    const int od0  = (tid & 3) * 8;      // 0/8/16/24

    for (int jt = 0; jt < N_TOK / BN; jt++) {
        const int c0 = jt * BN;
        // load v tile in BOTH layouts
        for (int i = tid; i < BN * DH / 4; i += 256) {
            int row = i >> 3;
            int k4  = (i & 7) * 4;
            float4 t4 = *reinterpret_cast<const float4*>(&vh[(size_t)(c0 + row) * DH + k4]);
            *reinterpret_cast<float4*>(&vs[row][k4]) = t4;
            vsT[k4 + 0][row] = t4.x; vsT[k4 + 1][row] = t4.y;
            vsT[k4 + 2][row] = t4.z; vsT[k4 + 3][row] = t4.w;
        }
        __syncthreads();

        // scores (pre-scaled): s[i][j] = (q*c)[r0+ty*4+i] . v[c0+tx*4+j]
        u64 s2[4][2] = {};                         // 4 rows x (2 packed cols)
#pragma unroll
        for (int k = 0; k < DH; k++) {
            float qv[4];
            *reinterpret_cast<float4*>(qv) =
                *reinterpret_cast<const float4*>(&qsT[k][ty * 4]);
            ulonglong2 vv = *reinterpret_cast<const ulonglong2*>(&vsT[k][tx * 4]);
#pragma unroll
            for (int i = 0; i < 4; i++) {
                u64 q2 = pack2(qv[i]);
                fma2(s2[i][0], q2, vv.x);
                fma2(s2[i][1], q2, vv.y);
            }
        }

        // mask + exp (unnormalized); write global + smem + row partial sums
#pragma unroll
        for (int i = 0; i < 4; i++) {
            const int r = ty * 4 + i;
            unsigned w = g_mask[(size_t)(r0 + r) * MWORDS + ((c0 + tx * 4) >> 5)];
            float s[4];
            unpack2(s2[i][0], s[0], s[1]);
            unpack2(s2[i][1], s[2], s[3]);
            float p[4];
            float psum = 0.f;
#pragma unroll
            for (int j = 0; j < 4; j++) {
                int bit = (tx * 4 + j) & 31;
                p[j] = ((w >> bit) & 1u) ? ex2f(s[j]) : 0.f;
                psum += p[j];
            }
            red[r][tx] = psum;
            *reinterpret_cast<float4*>(&ps[r][tx * 4]) =
                make_float4(p[0], p[1], p[2], p[3]);
            if (write_attn) {
                *reinterpret_cast<float4*>(
                    &attn_out[((size_t)(h * N_TOK) + r0 + r) * N_TOK + c0 + tx * 4])
                    = make_float4(p[0], p[1], p[2], p[3]);
            }
        }
        __syncthreads();

        if (tid < BM) {
            float t = 0.f;
#pragma unroll
            for (int q2i = 0; q2i < 16; q2i++) t += red[tid][q2i];
            l_s[tid] += t;
        }

        // o += p_tile @ v_tile  (thread owns (orow, od0..od0+7); FFMA2)
#pragma unroll
        for (int c4 = 0; c4 < BN; c4 += 4) {
            float a[4];
            *reinterpret_cast<float4*>(a) =
                *reinterpret_cast<const float4*>(&ps[orow][c4]);
#pragma unroll
            for (int u = 0; u < 4; u++) {
                ulonglong2 v0 = *reinterpret_cast<const ulonglong2*>(&vs[c4 + u][od0]);
                ulonglong2 v1 = *reinterpret_cast<const ulonglong2*>(&vs[c4 + u][od0 + 4]);
                u64 a2 = pack2(a[u]);
                fma2(o2[0], a2, v0.x);
                fma2(o2[1], a2, v0.y);
                fma2(o2[2], a2, v1.x);
                fma2(o2[3], a2, v1.y);
            }
        }
        __syncthreads();
    }

    // finalize l -> 1/l
    if (tid < BM) l_s[tid] = 1.0f / l_s[tid];
    __syncthreads();

    // o epilogue (normalized, float4 stores)
    {
        const float li = l_s[orow];
        float o[8];
        unpack2(o2[0], o[0], o[1]);
        unpack2(o2[1], o[2], o[3]);
        unpack2(o2[2], o[4], o[5]);
        unpack2(o2[3], o[6], o[7]);
#pragma unroll
        for (int j = 0; j < 8; j++) o[j] *= li;
        float* dst = &g_otmp[(size_t)(r0 + orow) * HID + h * DH + od0];
        *reinterpret_cast<float4*>(dst)     = make_float4(o[0], o[1], o[2], o[3]);
        *reinterpret_cast<float4*>(dst + 4) = make_float4(o[4], o[5], o[6], o[7]);
    }

    // fused normalize of this block's own attn stripe (block-local, L2-warm;
    // same-block global writes are visible after __syncthreads)
    if (write_attn) {
        float4* base = reinterpret_cast<float4*>(
            attn_out + ((size_t)(h * N_TOK) + r0) * N_TOK);
        for (int i = tid; i < BM * (N_TOK / 4); i += 256) {
            const float li = l_s[i >> 10];          // 1024 float4 per row
            float4 v = base[i];
            v.x *= li; v.y *= li; v.z *= li; v.w *= li;
            base[i] = v;
        }
    }
}

// ---------------------------------------------------------------- K3: wo linear
__global__ __launch_bounds__(256) void wo_kernel(
    float* __restrict__ out,
    const float* __restrict__ wo_w, const float* __restrict__ wo_b)
{
    linear_tile(g_otmp, wo_w, wo_b, out, 2,
                (blockIdx.x >> 2) * 64, (blockIdx.x & 3) * 64, threadIdx.x);
}

// ---------------------------------------------------------------- launch
extern "C" void kernel_launch(void* const* d_in, const int* in_sizes, int n_in,
                              void* d_out, int out_size)
{
    const float* x    = (const float*)d_in[0];
    const int*   Adj  = (const int*)  d_in[1];
    const float* wq_w = (const float*)d_in[2];
    const float* wq_b = (const float*)d_in[3];
    // d_in[4], d_in[5] = wk (dead in reference: scores use V)
    const float* wv_w = (const float*)d_in[6];
    const float* wv_b = (const float*)d_in[7];
    const float* wo_w = (const float*)d_in[8];
    const float* wo_b = (const float*)d_in[9];
    float* out = (float*)d_out;

    const long long need = (long long)N_TOK * HID + (long long)HEADS * N_TOK * N_TOK;
    int write_attn = ((long long)out_size >= need) ? 1 : 0;
    float* attn_out = out + (size_t)N_TOK * HID;

    qv_pack_kernel<<<dim3(96, 4, 2), 256>>>(x, wq_w, wq_b, wv_w, wv_b, Adj);
    attn_kernel<<<dim3(N_TOK / BM, HEADS), 256>>>(attn_out, write_attn);
    wo_kernel<<<256, 256>>>(out, wo_w, wo_b);
}